// round 7
// baseline (speedup 1.0000x reference)
#include <cuda_runtime.h>
#include <stdint.h>

// BinarizedLinear: act[d,o] = sum_i W[d,o,i] * x[d,i];  out[d,o] = (act > bias[d,o]) ? 1.0 : 0.0
// D=64, OUT=2048, IN=2048. All buffers float32.
//
// R7: clean persistence test. R6's regression was the xv[16] register cache
// (regs 124 -> occ 23.6%), NOT persistence. This keeps R2's exact inner stream
// (16 LDG.128 + LDS x-reads, regs ~37) but in a 1024-CTA single-wave grid:
// x staged once per 128 rows instead of once per 8, no wave-boundary bubbles.

#define D_DIRS 64
#define OUT_F  2048
#define IN_F   2048
#define WARPS  8
#define THREADS (WARPS * 32)
#define BLOCKS_PER_D 16                       // 2048 rows / 128 rows-per-block
#define ROWS_PER_BLOCK 128
#define TILES  (ROWS_PER_BLOCK / WARPS)       // 16 rows per warp

__global__ __launch_bounds__(THREADS)
void binlin_kernel(const float* __restrict__ W,
                   const float* __restrict__ x,
                   const float* __restrict__ bias,
                   float* __restrict__ out)
{
    __shared__ float xf[IN_F];

    const int d     = blockIdx.x / BLOCKS_PER_D;
    const int rbase = (blockIdx.x % BLOCKS_PER_D) * ROWS_PER_BLOCK;

    // Stage x[d,:] once per block (read-only afterwards -> single sync).
    const float4* xr4 = (const float4*)(x + (size_t)d * IN_F);
    float4*       xs4 = (float4*)xf;
    #pragma unroll
    for (int i = threadIdx.x; i < IN_F / 4; i += THREADS)
        xs4[i] = xr4[i];
    __syncthreads();

    const int warp = threadIdx.x >> 5;
    const int lane = threadIdx.x & 31;

    #pragma unroll 1
    for (int t = 0; t < TILES; ++t) {
        const int o = rbase + t * WARPS + warp;
        const float4* __restrict__ wr =
            (const float4*)(W + ((size_t)d * OUT_F + o) * IN_F);

        // R2's inner stream verbatim: 16 outstanding LDG.128 + smem x reads.
        float acc = 0.0f;
        #pragma unroll
        for (int it = 0; it < 16; ++it) {
            float4 w  = __ldg(&wr[it * 32 + lane]);
            float4 xv = *(const float4*)(&xf[it * 128 + lane * 4]);
            acc = fmaf(w.x, xv.x, acc);
            acc = fmaf(w.y, xv.y, acc);
            acc = fmaf(w.z, xv.z, acc);
            acc = fmaf(w.w, xv.w, acc);
        }

        #pragma unroll
        for (int s = 16; s > 0; s >>= 1)
            acc += __shfl_xor_sync(0xFFFFFFFFu, acc, s);

        if (lane == 0) {
            const int idx = d * OUT_F + o;
            out[idx] = (acc > bias[idx]) ? 1.0f : 0.0f;
        }
    }
}

extern "C" void kernel_launch(void* const* d_in, const int* in_sizes, int n_in,
                              void* d_out, int out_size)
{
    const float* W    = (const float*)d_in[0];
    const float* x    = (const float*)d_in[1];
    const float* bias = (const float*)d_in[2];
    float*       out  = (float*)d_out;

    const int grid = D_DIRS * BLOCKS_PER_D;   // 1024 CTAs -> single wave
    binlin_kernel<<<grid, THREADS>>>(W, x, bias, out);
}

// round 8
// speedup vs baseline: 11.4276x; 11.4276x over previous
#include <cuda_runtime.h>
#include <stdint.h>

// BinarizedLinear: act[d,o] = sum_i W[d,o,i] * x[d,i];  out[d,o] = (act > bias[d,o]) ? 1.0 : 0.0
// D=64, OUT=2048, IN=2048. All buffers float32 (0/1-valued W and x).
//
// R8: algorithmic byte reduction on top of the roofline R2 stream.
//   Exact bound: act[d,o] <= count[d] = sum_i x[d,i]  (W,x are 0/1).
//   If count[d] <= bias[d,o], then act > bias is impossible -> out = 0 without
//   reading the 8 KB weight row. For this data (count ~ 1024 +/- 22.6,
//   bias ~ 1024 +/- 0.5) about half the directions skip entirely.
//   Pre-kernel computes count[d]; main kernel = R2's 93%-DRAM stream + precheck.

#define D_DIRS 64
#define OUT_F  2048
#define IN_F   2048
#define ROWS_PER_BLOCK 8
#define THREADS (ROWS_PER_BLOCK * 32)

__device__ float g_count[D_DIRS];   // scratch: per-direction popcount of x

__global__ __launch_bounds__(256)
void count_kernel(const float* __restrict__ x)
{
    const int d = blockIdx.x;
    float s = 0.0f;
    #pragma unroll
    for (int i = threadIdx.x; i < IN_F; i += 256)
        s += x[(size_t)d * IN_F + i];
    #pragma unroll
    for (int off = 16; off > 0; off >>= 1)
        s += __shfl_xor_sync(0xFFFFFFFFu, s, off);

    __shared__ float ws[8];
    if ((threadIdx.x & 31) == 0) ws[threadIdx.x >> 5] = s;
    __syncthreads();
    if (threadIdx.x == 0) {
        float t = 0.0f;
        #pragma unroll
        for (int w = 0; w < 8; ++w) t += ws[w];
        g_count[d] = t;
    }
}

__global__ __launch_bounds__(THREADS)
void binlin_kernel(const float* __restrict__ W,
                   const float* __restrict__ x,
                   const float* __restrict__ bias,
                   float* __restrict__ out)
{
    __shared__ float xf[IN_F];

    const int d     = blockIdx.x >> 8;          // 256 blocks per direction
    const int obase = (blockIdx.x & 255) * ROWS_PER_BLOCK;

    const int warp = threadIdx.x >> 5;
    const int lane = threadIdx.x & 31;
    const int o    = obase + warp;
    const int idx  = d * OUT_F + o;

    // Exact skip test: act <= count[d], so count <= bias  =>  out = 0.
    const float b    = bias[idx];
    const float cnt  = g_count[d];
    const bool  skip = (cnt <= b);

    // If every warp in the block skips, exit without staging x.
    if (!__syncthreads_or(!skip)) {
        if (lane == 0) out[idx] = 0.0f;
        return;
    }

    // Stage x[d,:] (0.0/1.0 floats) in smem, vectorized 16B copies.
    const float4* xr4 = (const float4*)(x + (size_t)d * IN_F);
    float4*       xs4 = (float4*)xf;
    #pragma unroll
    for (int i = threadIdx.x; i < IN_F / 4; i += THREADS)
        xs4[i] = xr4[i];
    __syncthreads();

    if (skip) {
        if (lane == 0) out[idx] = 0.0f;
        return;
    }

    // R2's roofline stream: 16 outstanding LDG.128 per lane over one 8 KB row.
    const float4* __restrict__ wr =
        (const float4*)(W + ((size_t)d * OUT_F + o) * IN_F);

    float acc = 0.0f;
    #pragma unroll
    for (int it = 0; it < 16; ++it) {
        float4 w  = __ldg(&wr[it * 32 + lane]);
        float4 xv = *(const float4*)(&xf[it * 128 + lane * 4]);
        acc = fmaf(w.x, xv.x, acc);
        acc = fmaf(w.y, xv.y, acc);
        acc = fmaf(w.z, xv.z, acc);
        acc = fmaf(w.w, xv.w, acc);
    }

    #pragma unroll
    for (int s = 16; s > 0; s >>= 1)
        acc += __shfl_xor_sync(0xFFFFFFFFu, acc, s);

    if (lane == 0)
        out[idx] = (acc > b) ? 1.0f : 0.0f;
}

extern "C" void kernel_launch(void* const* d_in, const int* in_sizes, int n_in,
                              void* d_out, int out_size)
{
    const float* W    = (const float*)d_in[0];
    const float* x    = (const float*)d_in[1];
    const float* bias = (const float*)d_in[2];
    float*       out  = (float*)d_out;

    count_kernel<<<D_DIRS, 256>>>(x);

    const int grid = (D_DIRS * OUT_F) / ROWS_PER_BLOCK;    // 16384
    binlin_kernel<<<grid, THREADS>>>(W, x, bias, out);
}

// round 9
// speedup vs baseline: 24.4954x; 2.1435x over previous
#include <cuda_runtime.h>
#include <stdint.h>

// BinarizedLinear: act[d,o] = sum_i W[d,o,i]*x[d,i]; out[d,o] = (act > bias[d,o]) ? 1 : 0
// D=64, OUT=2048, IN=2048.
//
// R9: single fused kernel. Exact bound act <= count[d] = sum_i x[d,i]:
// count <= bias  =>  out = 0 without reading the 8 KB weight row. Measured (R8):
// this dataset skips ~everything (DRAM 0.4%), so the kernel is overhead-bound.
// Changes vs R8: one launch instead of two (count computed in-block from an 8 KB
// x read, staged to smem), 128 fat blocks instead of 16384 tiny ones, float4
// bias reads + float4 zero stores. Warp-cooperative exact fallback for any
// non-skipped row (R2's 93%-DRAM inner stream), so worst case stays correct.

#define D_DIRS 64
#define OUT_F  2048
#define IN_F   2048
#define THREADS 256
#define HALves_PER_D 2                 // 2 blocks per direction, 1024 outputs each

__global__ __launch_bounds__(THREADS)
void binlin_fused(const float* __restrict__ W,
                  const float* __restrict__ x,
                  const float* __restrict__ bias,
                  float* __restrict__ out)
{
    __shared__ float xf[IN_F];
    __shared__ float ws[8];
    __shared__ float s_cnt;

    const int d     = blockIdx.x >> 1;
    const int obase = (blockIdx.x & 1) << 10;   // 0 or 1024

    // Stage x[d,:] to smem and compute count[d] in one pass (8 KB).
    const float4* xr4 = (const float4*)(x + (size_t)d * IN_F);
    float4*       xs4 = (float4*)xf;
    float s = 0.0f;
    #pragma unroll
    for (int i = threadIdx.x; i < IN_F / 4; i += THREADS) {   // 2 iters
        float4 v = __ldg(&xr4[i]);
        xs4[i] = v;
        s += (v.x + v.y) + (v.z + v.w);
    }
    #pragma unroll
    for (int off = 16; off > 0; off >>= 1)
        s += __shfl_xor_sync(0xFFFFFFFFu, s, off);
    if ((threadIdx.x & 31) == 0) ws[threadIdx.x >> 5] = s;
    __syncthreads();
    if (threadIdx.x == 0) {
        float t = 0.0f;
        #pragma unroll
        for (int w = 0; w < 8; ++w) t += ws[w];
        s_cnt = t;
    }
    __syncthreads();
    const float cnt = s_cnt;

    const int lane = threadIdx.x & 31;

    // Each thread owns 4 consecutive outputs (float4-aligned).
    const int o0   = obase + threadIdx.x * 4;
    const int idx0 = d * OUT_F + o0;
    const float4 b4 = __ldg((const float4*)bias + (idx0 >> 2));

    unsigned flags = 0;
    if (cnt > b4.x) flags |= 1u;
    if (cnt > b4.y) flags |= 2u;
    if (cnt > b4.z) flags |= 4u;
    if (cnt > b4.w) flags |= 8u;

    // Fast path: zero all 4 outputs in one 16B store.
    float4 z; z.x = z.y = z.z = z.w = 0.0f;
    ((float4*)out)[idx0 >> 2] = z;

    // Exact fallback: warp cooperatively computes any row where count > bias.
    unsigned m = __ballot_sync(0xFFFFFFFFu, flags != 0);
    while (m) {
        const int src = __ffs(m) - 1;
        m &= m - 1u;
        const unsigned f     = __shfl_sync(0xFFFFFFFFu, flags, src);
        const int      sidx0 = __shfl_sync(0xFFFFFFFFu, idx0, src);

        #pragma unroll
        for (int j = 0; j < 4; ++j) {
            if (!(f & (1u << j))) continue;
            const int row = sidx0 + j;
            const float4* __restrict__ wr =
                (const float4*)W + (size_t)row * (IN_F / 4);

            float acc = 0.0f;
            #pragma unroll
            for (int it = 0; it < 16; ++it) {
                float4 w  = __ldg(&wr[it * 32 + lane]);
                float4 xv = *(const float4*)(&xf[it * 128 + lane * 4]);
                acc = fmaf(w.x, xv.x, acc);
                acc = fmaf(w.y, xv.y, acc);
                acc = fmaf(w.z, xv.z, acc);
                acc = fmaf(w.w, xv.w, acc);
            }
            #pragma unroll
            for (int off = 16; off > 0; off >>= 1)
                acc += __shfl_xor_sync(0xFFFFFFFFu, acc, off);

            if (lane == src) {    // owner thread: overwrite its zero (program order)
                const float bv = (j == 0) ? b4.x : (j == 1) ? b4.y
                               : (j == 2) ? b4.z : b4.w;
                out[row] = (acc > bv) ? 1.0f : 0.0f;
            }
        }
    }
}

extern "C" void kernel_launch(void* const* d_in, const int* in_sizes, int n_in,
                              void* d_out, int out_size)
{
    const float* W    = (const float*)d_in[0];
    const float* x    = (const float*)d_in[1];
    const float* bias = (const float*)d_in[2];
    float*       out  = (float*)d_out;

    binlin_fused<<<D_DIRS * HALves_PER_D, THREADS>>>(W, x, bias, out);  // 128 blocks
}

// round 10
// speedup vs baseline: 24.6093x; 1.0047x over previous
#include <cuda_runtime.h>
#include <stdint.h>

// BinarizedLinear: act[d,o] = sum_i W[d,o,i]*x[d,i]; out[d,o] = (act > bias[d,o]) ? 1 : 0
// D=64, OUT=2048, IN=2048.
//
// R10: sync-free variant of the fused skip kernel.
//   Exact bound: act <= count[d] = sum_i x[d,i]; count <= bias => out = 0 without
//   reading the 8 KB weight row (measured: this dataset skips ~everything).
//   Each WARP computes count[d] autonomously (16 float4 x-loads per lane, L2-hit,
//   5-shfl reduce) -> no smem, no __syncthreads, no cross-warp critical path.
//   Exact warp-cooperative fallback (R2's 93%-DRAM stream, x from L2) for any
//   row where count > bias, so worst-case data stays correct at ~R2 speed.

#define D_DIRS 64
#define OUT_F  2048
#define IN_F   2048
#define THREADS 256                       // 8 warps, 4 outputs per thread
#define BLOCKS  (D_DIRS * 2)              // 2 blocks per direction (1024 outputs each)

__global__ __launch_bounds__(THREADS)
void binlin_fused(const float* __restrict__ W,
                  const float* __restrict__ x,
                  const float* __restrict__ bias,
                  float* __restrict__ out)
{
    const int d     = blockIdx.x >> 1;
    const int obase = (blockIdx.x & 1) << 10;   // 0 or 1024
    const int lane  = threadIdx.x & 31;

    // Warp-autonomous count[d]: stream the full x row (512 float4, 16/lane).
    const float4* __restrict__ xr = (const float4*)x + (size_t)d * (IN_F / 4);
    float s = 0.0f;
    #pragma unroll
    for (int it = 0; it < 16; ++it) {
        float4 v = __ldg(&xr[it * 32 + lane]);
        s += (v.x + v.y) + (v.z + v.w);
    }
    #pragma unroll
    for (int off = 16; off > 0; off >>= 1)
        s += __shfl_xor_sync(0xFFFFFFFFu, s, off);
    const float cnt = s;                        // identical in all lanes

    // Each thread owns 4 consecutive outputs (float4-aligned).
    const int o0   = obase + threadIdx.x * 4;
    const int idx0 = d * OUT_F + o0;
    const float4 b4 = __ldg((const float4*)bias + (idx0 >> 2));

    unsigned flags = 0;
    if (cnt > b4.x) flags |= 1u;
    if (cnt > b4.y) flags |= 2u;
    if (cnt > b4.z) flags |= 4u;
    if (cnt > b4.w) flags |= 8u;

    // Fast path: zero all 4 outputs in one 16B store.
    float4 z; z.x = z.y = z.z = z.w = 0.0f;
    ((float4*)out)[idx0 >> 2] = z;

    // Exact fallback: warp cooperatively computes any row where count > bias.
    unsigned m = __ballot_sync(0xFFFFFFFFu, flags != 0);
    while (m) {
        const int src = __ffs(m) - 1;
        m &= m - 1u;
        const unsigned f     = __shfl_sync(0xFFFFFFFFu, flags, src);
        const int      sidx0 = __shfl_sync(0xFFFFFFFFu, idx0, src);

        #pragma unroll
        for (int j = 0; j < 4; ++j) {
            if (!(f & (1u << j))) continue;
            const int row = sidx0 + j;
            const float4* __restrict__ wr =
                (const float4*)W + (size_t)row * (IN_F / 4);

            float acc = 0.0f;
            #pragma unroll
            for (int it = 0; it < 16; ++it) {
                float4 w  = __ldg(&wr[it * 32 + lane]);
                float4 xv = __ldg(&xr[it * 32 + lane]);   // L2-resident
                acc = fmaf(w.x, xv.x, acc);
                acc = fmaf(w.y, xv.y, acc);
                acc = fmaf(w.z, xv.z, acc);
                acc = fmaf(w.w, xv.w, acc);
            }
            #pragma unroll
            for (int off = 16; off > 0; off >>= 1)
                acc += __shfl_xor_sync(0xFFFFFFFFu, acc, off);

            if (lane == src) {    // owner overwrites its zero (program order)
                const float bv = (j == 0) ? b4.x : (j == 1) ? b4.y
                               : (j == 2) ? b4.z : b4.w;
                out[row] = (acc > bv) ? 1.0f : 0.0f;
            }
        }
    }
}

extern "C" void kernel_launch(void* const* d_in, const int* in_sizes, int n_in,
                              void* d_out, int out_size)
{
    const float* W    = (const float*)d_in[0];
    const float* x    = (const float*)d_in[1];
    const float* bias = (const float*)d_in[2];
    float*       out  = (float*)d_out;

    binlin_fused<<<BLOCKS, THREADS>>>(W, x, bias, out);   // 128 blocks, 1 launch
}

// round 11
// speedup vs baseline: 25.5604x; 1.0386x over previous
#include <cuda_runtime.h>
#include <stdint.h>

// BinarizedLinear: act[d,o] = sum_i W[d,o,i]*x[d,i]; out[d,o] = (act > bias[d,o]) ? 1 : 0
// D=64, OUT=2048, IN=2048.
//
// R11: overhead-floor probe. Exact bound act <= count[d] = sum_i x[d,i];
// count <= bias => out = 0 without reading the 8 KB weight row (measured:
// this dataset skips everything; DRAM ~2%). Two prior kernels with 4.4us and
// 6.2us ncu times both hit 6.9us wall => wall is harness replay floor.
// This round: 256 CTAs (>148 SMs, shorter tail), 512 outputs/CTA via float2,
// sync-free per-warp count, exact warp-cooperative fallback for count > bias.

#define D_DIRS 64
#define OUT_F  2048
#define IN_F   2048
#define THREADS 256                        // 8 warps, 2 outputs per thread
#define BLOCKS_PER_D 4                     // 512 outputs per block
#define BLOCKS  (D_DIRS * BLOCKS_PER_D)    // 256 CTAs

__global__ __launch_bounds__(THREADS)
void binlin_fused(const float* __restrict__ W,
                  const float* __restrict__ x,
                  const float* __restrict__ bias,
                  float* __restrict__ out)
{
    const int d     = blockIdx.x >> 2;
    const int obase = (blockIdx.x & 3) << 9;    // 0/512/1024/1536
    const int lane  = threadIdx.x & 31;

    // Warp-autonomous count[d]: 16 back-to-back LDG.128 per lane (L2-hot x),
    // then a 5-shfl butterfly. No smem, no barriers.
    const float4* __restrict__ xr = (const float4*)x + (size_t)d * (IN_F / 4);
    float s = 0.0f;
    #pragma unroll
    for (int it = 0; it < 16; ++it) {
        float4 v = __ldg(&xr[it * 32 + lane]);
        s += (v.x + v.y) + (v.z + v.w);
    }
    #pragma unroll
    for (int off = 16; off > 0; off >>= 1)
        s += __shfl_xor_sync(0xFFFFFFFFu, s, off);
    const float cnt = s;                        // identical in all lanes

    // Each thread owns 2 consecutive outputs (float2-aligned).
    const int o0   = obase + threadIdx.x * 2;
    const int idx0 = d * OUT_F + o0;
    const float2 b2 = __ldg((const float2*)bias + (idx0 >> 1));

    unsigned flags = 0;
    if (cnt > b2.x) flags |= 1u;
    if (cnt > b2.y) flags |= 2u;

    // Fast path: zero both outputs in one 8B store.
    float2 z; z.x = z.y = 0.0f;
    ((float2*)out)[idx0 >> 1] = z;

    // Exact fallback: warp cooperatively computes any row where count > bias.
    unsigned m = __ballot_sync(0xFFFFFFFFu, flags != 0);
    while (m) {
        const int src = __ffs(m) - 1;
        m &= m - 1u;
        const unsigned f     = __shfl_sync(0xFFFFFFFFu, flags, src);
        const int      sidx0 = __shfl_sync(0xFFFFFFFFu, idx0, src);

        #pragma unroll
        for (int j = 0; j < 2; ++j) {
            if (!(f & (1u << j))) continue;
            const int row = sidx0 + j;
            const float4* __restrict__ wr =
                (const float4*)W + (size_t)row * (IN_F / 4);

            float acc = 0.0f;
            #pragma unroll
            for (int it = 0; it < 16; ++it) {
                float4 w  = __ldg(&wr[it * 32 + lane]);
                float4 xv = __ldg(&xr[it * 32 + lane]);   // L2-resident
                acc = fmaf(w.x, xv.x, acc);
                acc = fmaf(w.y, xv.y, acc);
                acc = fmaf(w.z, xv.z, acc);
                acc = fmaf(w.w, xv.w, acc);
            }
            #pragma unroll
            for (int off = 16; off > 0; off >>= 1)
                acc += __shfl_xor_sync(0xFFFFFFFFu, acc, off);

            if (lane == src) {    // owner overwrites its zero (program order)
                const float bv = (j == 0) ? b2.x : b2.y;
                out[row] = (acc > bv) ? 1.0f : 0.0f;
            }
        }
    }
}

extern "C" void kernel_launch(void* const* d_in, const int* in_sizes, int n_in,
                              void* d_out, int out_size)
{
    const float* W    = (const float*)d_in[0];
    const float* x    = (const float*)d_in[1];
    const float* bias = (const float*)d_in[2];
    float*       out  = (float*)d_out;

    binlin_fused<<<BLOCKS, THREADS>>>(W, x, bias, out);   // 256 CTAs, 1 launch
}